// round 1
// baseline (speedup 1.0000x reference)
#include <cuda_runtime.h>
#include <math.h>

#define BB 2
#define SS 2048
#define DD 1024
#define HH 16
#define DHH 64
#define MTOK (BB*SS)      /* 4096 tokens */
#define DFF (4*DD)        /* 4096 */

// ---------------- scratch (no allocations allowed) ----------------
__device__ float g_Wpack[(size_t)DD * 3 * DD];          // [D, 3D] packed qkv weights
__device__ float g_bpack[3 * DD];
__device__ float g_QKV[(size_t)MTOK * 3 * DD];          // [tok, 3D]  (q | k | v), col = which*D + h*64 + e
__device__ float g_scores[(size_t)BB * HH * SS * SS];   // 512 MB
__device__ float g_attn[(size_t)MTOK * DD];             // attn output, [b,s,h,e] == [tok, D]
__device__ float g_x1[(size_t)MTOK * DD];
__device__ float g_h1[(size_t)MTOK * DFF];
__device__ float g_ffn[(size_t)MTOK * DD];

// ---------------- weight repack: [H,D,Dh] x3 -> [D, 3D] ----------------
__global__ void pack_w(const float* __restrict__ Wq, const float* __restrict__ Wk,
                       const float* __restrict__ Wv, const float* __restrict__ bq,
                       const float* __restrict__ bk, const float* __restrict__ bv) {
    int idx = blockIdx.x * blockDim.x + threadIdx.x;
    int total = 3 * DD * DD;
    if (idx < total) {
        int which = idx / (DD * DD);
        int rem   = idx % (DD * DD);
        int d = rem / DD;
        int c = rem % DD;                  // c = h*64 + e
        const float* W = (which == 0) ? Wq : (which == 1) ? Wk : Wv;
        g_Wpack[(size_t)d * (3 * DD) + which * DD + c] =
            W[(size_t)(c / DHH) * (DD * DHH) + (size_t)d * DHH + (c % DHH)];
    }
    if (idx < 3 * DD) {
        int which = idx / DD;
        int c = idx % DD;
        const float* bb = (which == 0) ? bq : (which == 1) ? bk : bv;
        g_bpack[idx] = bb[c];
    }
}

// ---------------- generic tiled SGEMM: C[M,N] = A[M,K] @ B[K,N] + bias ----------------
// 128x128 block tile, BK=8, 256 threads, 8x8 per thread. M%128==0, N%128==0, K%8==0 assumed.
template <bool RELU>
__global__ void sgemm(const float* __restrict__ A, const float* __restrict__ Bm,
                      const float* __restrict__ bias, float* __restrict__ C,
                      int M, int N, int K) {
    __shared__ float As[8][128];
    __shared__ float Bs[8][128];
    int tid = threadIdx.x;
    int m0 = blockIdx.y * 128;
    int n0 = blockIdx.x * 128;
    int ty = tid >> 4, tx = tid & 15;
    int arow = tid >> 1;            // 0..127
    int acol = (tid & 1) * 4;       // 0 or 4
    int brow = tid >> 5;            // 0..7
    int bcol = (tid & 31) * 4;      // 0..124
    float acc[8][8];
#pragma unroll
    for (int i = 0; i < 8; i++)
#pragma unroll
        for (int j = 0; j < 8; j++) acc[i][j] = 0.f;

    for (int k0 = 0; k0 < K; k0 += 8) {
        float4 av = *(const float4*)(A + (size_t)(m0 + arow) * K + k0 + acol);
        As[acol + 0][arow] = av.x; As[acol + 1][arow] = av.y;
        As[acol + 2][arow] = av.z; As[acol + 3][arow] = av.w;
        float4 bv4 = *(const float4*)(Bm + (size_t)(k0 + brow) * N + n0 + bcol);
        *(float4*)&Bs[brow][bcol] = bv4;
        __syncthreads();
#pragma unroll
        for (int kk = 0; kk < 8; kk++) {
            float a[8], b[8];
#pragma unroll
            for (int i = 0; i < 8; i++) a[i] = As[kk][ty * 8 + i];
#pragma unroll
            for (int j = 0; j < 8; j++) b[j] = Bs[kk][tx * 8 + j];
#pragma unroll
            for (int i = 0; i < 8; i++)
#pragma unroll
                for (int j = 0; j < 8; j++) acc[i][j] += a[i] * b[j];
        }
        __syncthreads();
    }
#pragma unroll
    for (int i = 0; i < 8; i++) {
        int m = m0 + ty * 8 + i;
#pragma unroll
        for (int j = 0; j < 8; j++) {
            int n = n0 + tx * 8 + j;
            float v = acc[i][j] + bias[n];
            if (RELU) v = fmaxf(v, 0.f);
            C[(size_t)m * N + n] = v;
        }
    }
}

// ---------------- attention scores: wei[bh, s, t] = 0.125 * q.k, masked ----------------
__global__ void attn_scores(const int* __restrict__ mask) {
    __shared__ float Qs[8][128];
    __shared__ float Ks[8][128];
    int tid = threadIdx.x;
    int bh = blockIdx.z;
    int b = bh / HH, h = bh % HH;
    int m0 = blockIdx.y * 128;
    int n0 = blockIdx.x * 128;
    const float* qbase = g_QKV + (size_t)b * SS * (3 * DD) + (size_t)h * DHH;
    const float* kbase = qbase + DD;
    int ty = tid >> 4, tx = tid & 15;
    int arow = tid >> 1;
    int acol = (tid & 1) * 4;
    float acc[8][8];
#pragma unroll
    for (int i = 0; i < 8; i++)
#pragma unroll
        for (int j = 0; j < 8; j++) acc[i][j] = 0.f;

    for (int k0 = 0; k0 < DHH; k0 += 8) {
        float4 qv = *(const float4*)(qbase + (size_t)(m0 + arow) * (3 * DD) + k0 + acol);
        Qs[acol + 0][arow] = qv.x; Qs[acol + 1][arow] = qv.y;
        Qs[acol + 2][arow] = qv.z; Qs[acol + 3][arow] = qv.w;
        float4 kv = *(const float4*)(kbase + (size_t)(n0 + arow) * (3 * DD) + k0 + acol);
        Ks[acol + 0][arow] = kv.x; Ks[acol + 1][arow] = kv.y;
        Ks[acol + 2][arow] = kv.z; Ks[acol + 3][arow] = kv.w;
        __syncthreads();
#pragma unroll
        for (int kk = 0; kk < 8; kk++) {
            float a[8], c[8];
#pragma unroll
            for (int i = 0; i < 8; i++) a[i] = Qs[kk][ty * 8 + i];
#pragma unroll
            for (int j = 0; j < 8; j++) c[j] = Ks[kk][tx * 8 + j];
#pragma unroll
            for (int i = 0; i < 8; i++)
#pragma unroll
                for (int j = 0; j < 8; j++) acc[i][j] += a[i] * c[j];
        }
        __syncthreads();
    }
    float* srow = g_scores + (size_t)bh * SS * SS;
    const int* mrow = mask + b * SS;
#pragma unroll
    for (int i = 0; i < 8; i++) {
        int m = m0 + ty * 8 + i;
#pragma unroll
        for (int j = 0; j < 8; j++) {
            int n = n0 + tx * 8 + j;
            float v = acc[i][j] * 0.125f;
            if (mrow[n] == 0) v = -INFINITY;
            srow[(size_t)m * SS + n] = v;
        }
    }
}

// ---------------- softmax over last axis, in place. one block per row ----------------
__global__ void softmax_rows() {
    size_t row = blockIdx.x;
    float* p = g_scores + row * SS;
    int tid = threadIdx.x;
    float vals[8];
    float lmax = -INFINITY;
#pragma unroll
    for (int i = 0; i < 8; i++) {
        vals[i] = p[tid + i * 256];
        lmax = fmaxf(lmax, vals[i]);
    }
    __shared__ float red[256];
    red[tid] = lmax;
    __syncthreads();
    for (int s = 128; s > 0; s >>= 1) {
        if (tid < s) red[tid] = fmaxf(red[tid], red[tid + s]);
        __syncthreads();
    }
    float mx = red[0];
    __syncthreads();
    float lsum = 0.f;
#pragma unroll
    for (int i = 0; i < 8; i++) {
        vals[i] = __expf(vals[i] - mx);
        lsum += vals[i];
    }
    red[tid] = lsum;
    __syncthreads();
    for (int s = 128; s > 0; s >>= 1) {
        if (tid < s) red[tid] += red[tid + s];
        __syncthreads();
    }
    float inv = 1.f / red[0];
#pragma unroll
    for (int i = 0; i < 8; i++) p[tid + i * 256] = vals[i] * inv;
}

// ---------------- attn @ v : [S,S] @ [S,64] per (b,h) ----------------
__global__ void attn_v() {
    __shared__ float Ws[16][128];
    __shared__ float Vs[16][64];
    int tid = threadIdx.x;
    int bh = blockIdx.z;
    int b = bh / HH, h = bh % HH;
    int m0 = blockIdx.y * 128;
    const float* srow = g_scores + (size_t)bh * SS * SS;
    const float* vbase = g_QKV + (size_t)b * SS * (3 * DD) + 2 * DD + (size_t)h * DHH;
    int ty = tid >> 4, tx = tid & 15;
    float acc[8][4];
#pragma unroll
    for (int i = 0; i < 8; i++)
#pragma unroll
        for (int j = 0; j < 4; j++) acc[i][j] = 0.f;

    for (int k0 = 0; k0 < SS; k0 += 16) {
#pragma unroll
        for (int u = 0; u < 2; u++) {
            int f = tid * 2 + u;            // 0..511
            int row = f >> 2;               // 0..127
            int c4 = (f & 3) * 4;           // 0,4,8,12
            float4 wv = *(const float4*)(srow + (size_t)(m0 + row) * SS + k0 + c4);
            Ws[c4 + 0][row] = wv.x; Ws[c4 + 1][row] = wv.y;
            Ws[c4 + 2][row] = wv.z; Ws[c4 + 3][row] = wv.w;
        }
        {
            int row = tid >> 4;             // 0..15
            int c4 = (tid & 15) * 4;        // 0..60
            float4 vv = *(const float4*)(vbase + (size_t)(k0 + row) * (3 * DD) + c4);
            *(float4*)&Vs[row][c4] = vv;
        }
        __syncthreads();
#pragma unroll
        for (int kk = 0; kk < 16; kk++) {
            float a[8], bv[4];
#pragma unroll
            for (int i = 0; i < 8; i++) a[i] = Ws[kk][ty * 8 + i];
#pragma unroll
            for (int j = 0; j < 4; j++) bv[j] = Vs[kk][tx * 4 + j];
#pragma unroll
            for (int i = 0; i < 8; i++)
#pragma unroll
                for (int j = 0; j < 4; j++) acc[i][j] += a[i] * bv[j];
        }
        __syncthreads();
    }
#pragma unroll
    for (int i = 0; i < 8; i++) {
        int m = m0 + ty * 8 + i;
#pragma unroll
        for (int j = 0; j < 4; j++) {
            g_attn[(size_t)(b * SS + m) * DD + h * DHH + tx * 4 + j] = acc[i][j];
        }
    }
}

// ---------------- out = xres + alpha * (a - mean)/(std_unbiased + eps) + beta ----------------
__global__ void add_ln(const float* __restrict__ xres, const float* __restrict__ a,
                       const float* __restrict__ alpha, const float* __restrict__ beta,
                       float* __restrict__ out) {
    int row = blockIdx.x;
    int tid = threadIdx.x;
    const float* ap = a + (size_t)row * DD;
    float v[4];
    float lsum = 0.f;
#pragma unroll
    for (int i = 0; i < 4; i++) {
        v[i] = ap[tid + i * 256];
        lsum += v[i];
    }
    __shared__ float red[256];
    red[tid] = lsum;
    __syncthreads();
    for (int s = 128; s > 0; s >>= 1) {
        if (tid < s) red[tid] += red[tid + s];
        __syncthreads();
    }
    float mean = red[0] * (1.f / DD);
    __syncthreads();
    float lss = 0.f;
#pragma unroll
    for (int i = 0; i < 4; i++) {
        float d = v[i] - mean;
        lss += d * d;
    }
    red[tid] = lss;
    __syncthreads();
    for (int s = 128; s > 0; s >>= 1) {
        if (tid < s) red[tid] += red[tid + s];
        __syncthreads();
    }
    float var = red[0] * (1.f / (DD - 1));     // unbiased (ddof=1)
    float inv = 1.f / (sqrtf(var) + 1e-6f);    // (std + eps)
#pragma unroll
    for (int i = 0; i < 4; i++) {
        int c = tid + i * 256;
        out[(size_t)row * DD + c] = xres[(size_t)row * DD + c] + alpha[c] * (v[i] - mean) * inv + beta[c];
    }
}

// ---------------- launch ----------------
extern "C" void kernel_launch(void* const* d_in, const int* in_sizes, int n_in,
                              void* d_out, int out_size) {
    const float* x      = (const float*)d_in[0];
    const int*   mask   = (const int*)d_in[1];
    const float* Wq     = (const float*)d_in[2];
    const float* bq     = (const float*)d_in[3];
    const float* Wk     = (const float*)d_in[4];
    const float* bk     = (const float*)d_in[5];
    const float* Wv     = (const float*)d_in[6];
    const float* bv     = (const float*)d_in[7];
    const float* W1     = (const float*)d_in[8];
    const float* b1     = (const float*)d_in[9];
    const float* W2     = (const float*)d_in[10];
    const float* b2     = (const float*)d_in[11];
    const float* alpha1 = (const float*)d_in[12];
    const float* beta1  = (const float*)d_in[13];
    const float* alpha2 = (const float*)d_in[14];
    const float* beta2  = (const float*)d_in[15];
    float* out = (float*)d_out;

    float *Wpack, *bpack, *QKV, *attn, *x1, *h1, *ffn;
    cudaGetSymbolAddress((void**)&Wpack, g_Wpack);
    cudaGetSymbolAddress((void**)&bpack, g_bpack);
    cudaGetSymbolAddress((void**)&QKV,   g_QKV);
    cudaGetSymbolAddress((void**)&attn,  g_attn);
    cudaGetSymbolAddress((void**)&x1,    g_x1);
    cudaGetSymbolAddress((void**)&h1,    g_h1);
    cudaGetSymbolAddress((void**)&ffn,   g_ffn);

    // 1. repack per-head weights -> [D, 3D]
    pack_w<<<(3 * DD * DD + 255) / 256, 256>>>(Wq, Wk, Wv, bq, bk, bv);

    // 2. QKV = x @ Wpack + bpack    [4096, 3072]
    sgemm<false><<<dim3((3 * DD) / 128, MTOK / 128), 256>>>(x, Wpack, bpack, QKV, MTOK, 3 * DD, DD);

    // 3. scores (scaled + masked)
    attn_scores<<<dim3(SS / 128, SS / 128, BB * HH), 256>>>(mask);

    // 4. softmax in place
    softmax_rows<<<BB * HH * SS, 256>>>();

    // 5. attn = softmax @ v  ->  [b,s,h,e] layout == [tok, D]
    attn_v<<<dim3(1, SS / 128, BB * HH), 256>>>();

    // 6. x1 = x + LN1(attn)
    add_ln<<<MTOK, 256>>>(x, attn, alpha1, beta1, x1);

    // 7. h1 = relu(x1 @ W1 + b1)   [4096, 4096]
    sgemm<true><<<dim3(DFF / 128, MTOK / 128), 256>>>(x1, W1, b1, h1, MTOK, DFF, DD);

    // 8. ffn = h1 @ W2 + b2        [4096, 1024]
    sgemm<false><<<dim3(DD / 128, MTOK / 128), 256>>>(h1, W2, b2, ffn, MTOK, DD, DFF);

    // 9. out = x1 + LN2(ffn)
    add_ln<<<MTOK, 256>>>(x1, ffn, alpha2, beta2, out);
}

// round 3
// speedup vs baseline: 3.3742x; 3.3742x over previous
#include <cuda_runtime.h>
#include <math.h>
#include <stdint.h>

#define BB 2
#define SS 2048
#define DD 1024
#define HH 16
#define DFF 4096
#define MTOK 4096

// ---------------- scratch (no allocations allowed) ----------------
__device__ float g_xr[(size_t)MTOK * DD];          // tf32-rounded x
__device__ float g_WpackT[(size_t)3 * DD * DD];    // [3D, D] K-major packed qkv weights (rounded)
__device__ float g_bpack[3 * DD];
__device__ float g_W1T[(size_t)DFF * DD];          // [4D, D] (rounded)
__device__ float g_W2T[(size_t)DD * DFF];          // [D, 4D] (rounded)
__device__ float g_QKV[(size_t)MTOK * 3 * DD];     // [tok, 3D] (rounded at epilogue)
__device__ float g_VT[(size_t)BB * HH * 64 * SS];  // [bh, 64, S]
__device__ float g_scores[(size_t)BB * HH * SS * SS];
__device__ float g_attn[(size_t)MTOK * DD];
__device__ float g_x1[(size_t)MTOK * DD];          // exact
__device__ float g_x1r[(size_t)MTOK * DD];         // rounded
__device__ float g_h1[(size_t)MTOK * DFF];         // rounded
__device__ float g_ffn[(size_t)MTOK * DD];

// ---------------- helpers ----------------
__device__ __forceinline__ uint32_t smem_u32(const void* p) {
    uint32_t a;
    asm("{ .reg .u64 t; cvta.to.shared.u64 t, %1; cvt.u32.u64 %0, t; }" : "=r"(a) : "l"(p));
    return a;
}
__device__ __forceinline__ float rndf(float f) {
    uint32_t u;
    asm("cvt.rna.tf32.f32 %0, %1;" : "=r"(u) : "f"(f));
    return __uint_as_float(u);
}
#define SWZ128(o) ((o) ^ (((o) >> 3) & 0x70))
#define CP16(dst, src) asm volatile("cp.async.cg.shared.global [%0], [%1], 16;" :: "r"(dst), "l"(src))

__device__ __forceinline__ void mma_tf32(float* d, const uint32_t* a, const uint32_t* b) {
    asm volatile(
        "mma.sync.aligned.m16n8k8.row.col.f32.tf32.tf32.f32 "
        "{%0,%1,%2,%3}, {%4,%5,%6,%7}, {%8,%9}, {%0,%1,%2,%3};"
        : "+f"(d[0]), "+f"(d[1]), "+f"(d[2]), "+f"(d[3])
        : "r"(a[0]), "r"(a[1]), "r"(a[2]), "r"(a[3]), "r"(b[0]), "r"(b[1]));
}

// ---------------- tf32 mma.sync GEMM ----------------
// C[M,N] = A[M,K] (row-major) @ B[N,K]^T (row-major, K-major) + epilogue
// MODE 0: +bias   1: relu(+bias)   2: *0.125 + mask->-inf   3: plain
template <int BN, int MODE, bool RND>
__global__ void __launch_bounds__(256)
mma_gemm(const float* __restrict__ A, int lda, long long sAb, long long sAh,
         const float* __restrict__ B, int ldb, long long sBb, long long sBh,
         float* __restrict__ C, int ldc, long long sCb, long long sCh,
         const float* __restrict__ bias, const int* __restrict__ mask, int K) {
    extern __shared__ char smem[];
    constexpr int ABYTES = 128 * 32 * 4;   // 16 KB per A buffer
    constexpr int BBYTES = BN * 32 * 4;
    constexpr int MT = (BN == 128) ? 4 : 2;

    const uint32_t sb = smem_u32(smem);
    int tid = threadIdx.x, wid = tid >> 5, lid = tid & 31;
    int z = blockIdx.z;
    int m0 = blockIdx.y * 128, n0 = blockIdx.x * BN;
    const float* Ap = A + (size_t)(z >> 4) * sAb + (size_t)(z & 15) * sAh;
    const float* Bp = B + (size_t)(z >> 4) * sBb + (size_t)(z & 15) * sBh;
    float* Cp       = C + (size_t)(z >> 4) * sCb + (size_t)(z & 15) * sCh;

    int wm0, wn0;
    if (BN == 128) { wm0 = (wid >> 2) * 64; wn0 = (wid & 3) * 32; }
    else           { wm0 = (wid >> 1) * 32; wn0 = (wid & 1) * 32; }

    float acc[MT][4][4];
#pragma unroll
    for (int i = 0; i < MT; i++)
#pragma unroll
        for (int j = 0; j < 4; j++)
#pragma unroll
            for (int r = 0; r < 4; r++) acc[i][j][r] = 0.f;

    const int NC = K >> 5;

    // ---- stage tile 0 ----
    {
        uint32_t ab = sb, bb = sb + 2 * ABYTES;
#pragma unroll
        for (int i = 0; i < 4; i++) {
            int q = tid + i * 256, row = q >> 3, cg = q & 7;
            CP16(ab + SWZ128(q * 16), Ap + (size_t)(m0 + row) * lda + cg * 4);
        }
#pragma unroll
        for (int i = 0; i < (BN * 8) / 256; i++) {
            int q = tid + i * 256, row = q >> 3, cg = q & 7;
            CP16(bb + SWZ128(q * 16), Bp + (size_t)(n0 + row) * ldb + cg * 4);
        }
        asm volatile("cp.async.commit_group;" ::: "memory");
    }

    for (int c = 0; c < NC; c++) {
        int buf = c & 1;
        if (c + 1 < NC) {
            int k0 = (c + 1) << 5;
            uint32_t ab = sb + (buf ^ 1) * ABYTES;
            uint32_t bb = sb + 2 * ABYTES + (buf ^ 1) * BBYTES;
#pragma unroll
            for (int i = 0; i < 4; i++) {
                int q = tid + i * 256, row = q >> 3, cg = q & 7;
                CP16(ab + SWZ128(q * 16), Ap + (size_t)(m0 + row) * lda + k0 + cg * 4);
            }
#pragma unroll
            for (int i = 0; i < (BN * 8) / 256; i++) {
                int q = tid + i * 256, row = q >> 3, cg = q & 7;
                CP16(bb + SWZ128(q * 16), Bp + (size_t)(n0 + row) * ldb + k0 + cg * 4);
            }
            asm volatile("cp.async.commit_group;" ::: "memory");
            asm volatile("cp.async.wait_group 1;" ::: "memory");
        } else {
            asm volatile("cp.async.wait_group 0;" ::: "memory");
        }
        __syncthreads();

        uint32_t ab = sb + buf * ABYTES;
        uint32_t bb = sb + 2 * ABYTES + buf * BBYTES;
        int i8 = lid & 7, t4 = lid >> 3;
        int g = lid >> 2, tc = lid & 3;
#pragma unroll
        for (int s = 0; s < 4; s++) {
            uint32_t af[MT][4];
#pragma unroll
            for (int mt = 0; mt < MT; mt++) {
                int row = wm0 + mt * 16 + i8 + (t4 & 1) * 8;
                uint32_t addr = ab + SWZ128(row * 128 + (2 * s + (t4 >> 1)) * 16);
                asm volatile("ldmatrix.sync.aligned.m8n8.x4.shared.b16 {%0,%1,%2,%3}, [%4];"
                             : "=r"(af[mt][0]), "=r"(af[mt][1]), "=r"(af[mt][2]), "=r"(af[mt][3])
                             : "r"(addr));
            }
            uint32_t bf[4][2];
#pragma unroll
            for (int nt = 0; nt < 4; nt++) {
                int n = wn0 + nt * 8 + g;
                int byte0 = n * 128 + s * 32 + tc * 4;
                uint32_t a0 = bb + SWZ128(byte0);
                uint32_t a1 = bb + SWZ128(byte0 + 16);
                asm volatile("ld.shared.b32 %0, [%1];" : "=r"(bf[nt][0]) : "r"(a0));
                asm volatile("ld.shared.b32 %0, [%1];" : "=r"(bf[nt][1]) : "r"(a1));
            }
#pragma unroll
            for (int mt = 0; mt < MT; mt++)
#pragma unroll
                for (int nt = 0; nt < 4; nt++)
                    mma_tf32(acc[mt][nt], af[mt], bf[nt]);
        }
        __syncthreads();
    }

    // ---- epilogue ----
    int g = lid >> 2, tc = lid & 3;
    const int* maskp = (MODE == 2) ? (mask + (z >> 4) * SS) : nullptr;
#pragma unroll
    for (int mt = 0; mt < MT; mt++) {
        int row = m0 + wm0 + mt * 16 + g;
#pragma unroll
        for (int nt = 0; nt < 4; nt++) {
            int col = n0 + wn0 + nt * 8 + tc * 2;
            float v00 = acc[mt][nt][0], v01 = acc[mt][nt][1];
            float v10 = acc[mt][nt][2], v11 = acc[mt][nt][3];
            if (MODE == 0 || MODE == 1) {
                float2 bv = *(const float2*)(bias + col);
                v00 += bv.x; v01 += bv.y; v10 += bv.x; v11 += bv.y;
                if (MODE == 1) {
                    v00 = fmaxf(v00, 0.f); v01 = fmaxf(v01, 0.f);
                    v10 = fmaxf(v10, 0.f); v11 = fmaxf(v11, 0.f);
                }
            } else if (MODE == 2) {
                v00 *= 0.125f; v01 *= 0.125f; v10 *= 0.125f; v11 *= 0.125f;
                int2 mv = *(const int2*)(maskp + col);
                if (mv.x == 0) { v00 = -INFINITY; v10 = -INFINITY; }
                if (mv.y == 0) { v01 = -INFINITY; v11 = -INFINITY; }
            }
            if (RND) {
                v00 = rndf(v00); v01 = rndf(v01); v10 = rndf(v10); v11 = rndf(v11);
            }
            *(float2*)(Cp + (size_t)row * ldc + col) = make_float2(v00, v01);
            *(float2*)(Cp + (size_t)(row + 8) * ldc + col) = make_float2(v10, v11);
        }
    }
}

// ---------------- prep kernels ----------------
__global__ void round_copy(const float* __restrict__ in, float* __restrict__ out, int n4) {
    int i = blockIdx.x * blockDim.x + threadIdx.x;
    if (i < n4) {
        float4 v = ((const float4*)in)[i];
        v.x = rndf(v.x); v.y = rndf(v.y); v.z = rndf(v.z); v.w = rndf(v.w);
        ((float4*)out)[i] = v;
    }
}

// per-head weights [H,D,Dh] -> packed transposed [3D, D] (K-major for MMA B), rounded
__global__ void pack_wT(const float* __restrict__ Wq, const float* __restrict__ Wk,
                        const float* __restrict__ Wv) {
    __shared__ float t[32][33];
    int zz = blockIdx.z;
    int which = zz / HH, h = zz % HH;
    const float* W = (which == 0) ? Wq : (which == 1) ? Wk : Wv;
    int d0 = blockIdx.x * 32, e0 = blockIdx.y * 32;
#pragma unroll
    for (int i = 0; i < 32; i += 8)
        t[threadIdx.y + i][threadIdx.x] =
            W[(size_t)h * (DD * 64) + (size_t)(d0 + threadIdx.y + i) * 64 + e0 + threadIdx.x];
    __syncthreads();
#pragma unroll
    for (int i = 0; i < 32; i += 8)
        g_WpackT[(size_t)(which * DD + h * 64 + e0 + threadIdx.y + i) * DD + d0 + threadIdx.x] =
            rndf(t[threadIdx.x][threadIdx.y + i]);
}

__global__ void pack_bias(const float* __restrict__ bq, const float* __restrict__ bk,
                          const float* __restrict__ bv) {
    int i = blockIdx.x * blockDim.x + threadIdx.x;
    if (i < 3 * DD) {
        int which = i / DD, c = i % DD;
        const float* b = (which == 0) ? bq : (which == 1) ? bk : bv;
        g_bpack[i] = b[c];
    }
}

// out[C,R] = round(in[R,C]^T)
__global__ void transpose_k(const float* __restrict__ in, float* __restrict__ out, int R, int C) {
    __shared__ float t[32][33];
    int c0 = blockIdx.x * 32, r0 = blockIdx.y * 32;
#pragma unroll
    for (int i = 0; i < 32; i += 8)
        t[threadIdx.y + i][threadIdx.x] = in[(size_t)(r0 + threadIdx.y + i) * C + c0 + threadIdx.x];
    __syncthreads();
#pragma unroll
    for (int i = 0; i < 32; i += 8)
        out[(size_t)(c0 + threadIdx.y + i) * R + r0 + threadIdx.x] = rndf(t[threadIdx.x][threadIdx.y + i]);
}

// g_VT[bh][e][s] = V from QKV (already rounded)
__global__ void v_transpose() {
    __shared__ float t[32][33];
    int z = blockIdx.z;
    int b = z >> 4, h = z & 15;
    int s0 = blockIdx.x * 32, e0 = blockIdx.y * 32;
#pragma unroll
    for (int i = 0; i < 32; i += 8)
        t[threadIdx.y + i][threadIdx.x] =
            g_QKV[(size_t)(b * SS + s0 + threadIdx.y + i) * (3 * DD) + 2 * DD + h * 64 + e0 + threadIdx.x];
    __syncthreads();
#pragma unroll
    for (int i = 0; i < 32; i += 8)
        g_VT[((size_t)z * 64 + e0 + threadIdx.y + i) * SS + s0 + threadIdx.x] = t[threadIdx.x][threadIdx.y + i];
}

// ---------------- softmax over last axis, in place (rounded output) ----------------
__global__ void softmax_rows() {
    size_t row = blockIdx.x;
    float* p = g_scores + row * SS;
    int tid = threadIdx.x;
    float vals[8];
    float lmax = -INFINITY;
#pragma unroll
    for (int i = 0; i < 8; i++) {
        vals[i] = p[tid + i * 256];
        lmax = fmaxf(lmax, vals[i]);
    }
    __shared__ float red[256];
    red[tid] = lmax;
    __syncthreads();
    for (int s = 128; s > 0; s >>= 1) {
        if (tid < s) red[tid] = fmaxf(red[tid], red[tid + s]);
        __syncthreads();
    }
    float mx = red[0];
    __syncthreads();
    float lsum = 0.f;
#pragma unroll
    for (int i = 0; i < 8; i++) {
        vals[i] = __expf(vals[i] - mx);
        lsum += vals[i];
    }
    red[tid] = lsum;
    __syncthreads();
    for (int s = 128; s > 0; s >>= 1) {
        if (tid < s) red[tid] += red[tid + s];
        __syncthreads();
    }
    float inv = 1.f / red[0];
#pragma unroll
    for (int i = 0; i < 8; i++) p[tid + i * 256] = rndf(vals[i] * inv);
}

// ---------------- out = xres + alpha*(a-mean)/(std_unbiased+eps) + beta ----------------
template <bool DUAL>
__global__ void add_ln(const float* __restrict__ xres, const float* __restrict__ a,
                       const float* __restrict__ alpha, const float* __restrict__ beta,
                       float* __restrict__ out, float* __restrict__ outr) {
    int row = blockIdx.x;
    int tid = threadIdx.x;
    const float* ap = a + (size_t)row * DD;
    float v[4];
    float lsum = 0.f;
#pragma unroll
    for (int i = 0; i < 4; i++) {
        v[i] = ap[tid + i * 256];
        lsum += v[i];
    }
    __shared__ float red[256];
    red[tid] = lsum;
    __syncthreads();
    for (int s = 128; s > 0; s >>= 1) {
        if (tid < s) red[tid] += red[tid + s];
        __syncthreads();
    }
    float mean = red[0] * (1.f / DD);
    __syncthreads();
    float lss = 0.f;
#pragma unroll
    for (int i = 0; i < 4; i++) {
        float d = v[i] - mean;
        lss += d * d;
    }
    red[tid] = lss;
    __syncthreads();
    for (int s = 128; s > 0; s >>= 1) {
        if (tid < s) red[tid] += red[tid + s];
        __syncthreads();
    }
    float var = red[0] * (1.f / (DD - 1));
    float inv = 1.f / (sqrtf(var) + 1e-6f);
#pragma unroll
    for (int i = 0; i < 4; i++) {
        int c = tid + i * 256;
        float o = xres[(size_t)row * DD + c] + alpha[c] * (v[i] - mean) * inv + beta[c];
        out[(size_t)row * DD + c] = o;
        if (DUAL) outr[(size_t)row * DD + c] = rndf(o);
    }
}

// ---------------- launch ----------------
extern "C" void kernel_launch(void* const* d_in, const int* in_sizes, int n_in,
                              void* d_out, int out_size) {
    const float* x      = (const float*)d_in[0];
    const int*   mask   = (const int*)d_in[1];
    const float* Wq     = (const float*)d_in[2];
    const float* bq     = (const float*)d_in[3];
    const float* Wk     = (const float*)d_in[4];
    const float* bk     = (const float*)d_in[5];
    const float* Wv     = (const float*)d_in[6];
    const float* bv     = (const float*)d_in[7];
    const float* W1     = (const float*)d_in[8];
    const float* b1     = (const float*)d_in[9];
    const float* W2     = (const float*)d_in[10];
    const float* b2     = (const float*)d_in[11];
    const float* alpha1 = (const float*)d_in[12];
    const float* beta1  = (const float*)d_in[13];
    const float* alpha2 = (const float*)d_in[14];
    const float* beta2  = (const float*)d_in[15];
    float* out = (float*)d_out;

    float *xr, *WpackT, *bpack, *W1T, *W2T, *QKV, *VT, *scores, *attn, *x1, *x1r, *h1, *ffn;
    cudaGetSymbolAddress((void**)&xr,     g_xr);
    cudaGetSymbolAddress((void**)&WpackT, g_WpackT);
    cudaGetSymbolAddress((void**)&bpack,  g_bpack);
    cudaGetSymbolAddress((void**)&W1T,    g_W1T);
    cudaGetSymbolAddress((void**)&W2T,    g_W2T);
    cudaGetSymbolAddress((void**)&QKV,    g_QKV);
    cudaGetSymbolAddress((void**)&VT,     g_VT);
    cudaGetSymbolAddress((void**)&scores, g_scores);
    cudaGetSymbolAddress((void**)&attn,   g_attn);
    cudaGetSymbolAddress((void**)&x1,     g_x1);
    cudaGetSymbolAddress((void**)&x1r,    g_x1r);
    cudaGetSymbolAddress((void**)&h1,     g_h1);
    cudaGetSymbolAddress((void**)&ffn,    g_ffn);

    const int SM128 = 2 * 16384 + 2 * 128 * 32 * 4;   // 65536
    const int SM64  = 2 * 16384 + 2 * 64 * 32 * 4;    // 49152
    cudaFuncSetAttribute(mma_gemm<128, 0, true>,  cudaFuncAttributeMaxDynamicSharedMemorySize, SM128);
    cudaFuncSetAttribute(mma_gemm<128, 0, false>, cudaFuncAttributeMaxDynamicSharedMemorySize, SM128);
    cudaFuncSetAttribute(mma_gemm<128, 1, true>,  cudaFuncAttributeMaxDynamicSharedMemorySize, SM128);
    cudaFuncSetAttribute(mma_gemm<128, 2, false>, cudaFuncAttributeMaxDynamicSharedMemorySize, SM128);
    cudaFuncSetAttribute(mma_gemm<64, 3, false>,  cudaFuncAttributeMaxDynamicSharedMemorySize, SM64);

    // prep
    round_copy<<<(MTOK * DD / 4 + 255) / 256, 256>>>(x, xr, MTOK * DD / 4);
    pack_wT<<<dim3(32, 2, 48), dim3(32, 8)>>>(Wq, Wk, Wv);
    pack_bias<<<12, 256>>>(bq, bk, bv);
    transpose_k<<<dim3(DFF / 32, DD / 32), dim3(32, 8)>>>(W1, W1T, DD, DFF);
    transpose_k<<<dim3(DD / 32, DFF / 32), dim3(32, 8)>>>(W2, W2T, DFF, DD);

    // QKV = xr @ WpackT^T + bias  [4096, 3072], rounded
    mma_gemm<128, 0, true><<<dim3(24, 32, 1), 256, SM128>>>(
        xr, DD, 0, 0, WpackT, DD, 0, 0, QKV, 3 * DD, 0, 0, bpack, nullptr, DD);

    v_transpose<<<dim3(64, 2, 32), dim3(32, 8)>>>();

    // scores = 0.125 * Q @ K^T (masked)  per bh
    mma_gemm<128, 2, false><<<dim3(16, 16, 32), 256, SM128>>>(
        QKV, 3 * DD, (long long)SS * 3 * DD, 64,
        QKV + DD, 3 * DD, (long long)SS * 3 * DD, 64,
        scores, SS, (long long)HH * SS * SS, (long long)SS * SS,
        nullptr, mask, 64);

    softmax_rows<<<BB * HH * SS, 256>>>();

    // attn = probs @ V  (via V^T, N=64)
    mma_gemm<64, 3, false><<<dim3(1, 16, 32), 256, SM64>>>(
        scores, SS, (long long)HH * SS * SS, (long long)SS * SS,
        VT, SS, (long long)HH * 64 * SS, (long long)64 * SS,
        attn, DD, (long long)SS * DD, 64,
        nullptr, nullptr, SS);

    // x1 = x + LN1(attn)  (exact + rounded copy)
    add_ln<true><<<MTOK, 256>>>(x, attn, alpha1, beta1, x1, x1r);

    // FFN1: relu(x1r @ W1 + b1), rounded
    mma_gemm<128, 1, true><<<dim3(32, 32, 1), 256, SM128>>>(
        x1r, DD, 0, 0, W1T, DD, 0, 0, h1, DFF, 0, 0, b1, nullptr, DD);

    // FFN2: h1 @ W2 + b2
    mma_gemm<128, 0, false><<<dim3(8, 32, 1), 256, SM128>>>(
        h1, DFF, 0, 0, W2T, DFF, 0, 0, ffn, DD, 0, 0, b2, nullptr, DFF);

    // out = x1 + LN2(ffn)
    add_ln<false><<<MTOK, 256>>>(x1, ffn, alpha2, beta2, out, nullptr);
}

// round 5
// speedup vs baseline: 4.2482x; 1.2590x over previous
#include <cuda_runtime.h>
#include <math.h>
#include <stdint.h>

#define BB 2
#define SS 2048
#define DD 1024
#define HH 16
#define DFF 4096
#define MTOK 4096

// ---------------- scratch (no allocations allowed) ----------------
__device__ float g_xr[(size_t)MTOK * DD];          // tf32-rounded x
__device__ float g_WpackT[(size_t)3 * DD * DD];    // [3D, D] K-major packed qkv weights (rounded)
__device__ float g_bpack[3 * DD];
__device__ float g_W1T[(size_t)DFF * DD];          // [4D, D] (rounded)
__device__ float g_W2T[(size_t)DD * DFF];          // [D, 4D] (rounded)
__device__ float g_QKV[(size_t)MTOK * 3 * DD];     // [tok, 3D] (rounded at epilogue)
__device__ float g_attn[(size_t)MTOK * DD];
__device__ float g_x1[(size_t)MTOK * DD];          // exact
__device__ float g_x1r[(size_t)MTOK * DD];         // rounded
__device__ float g_h1[(size_t)MTOK * DFF];         // rounded
__device__ float g_ffn[(size_t)MTOK * DD];

// ---------------- helpers ----------------
__device__ __forceinline__ uint32_t smem_u32(const void* p) {
    uint32_t a;
    asm("{ .reg .u64 t; cvta.to.shared.u64 t, %1; cvt.u32.u64 %0, t; }" : "=r"(a) : "l"(p));
    return a;
}
__device__ __forceinline__ float rndf(float f) {
    uint32_t u;
    asm("cvt.rna.tf32.f32 %0, %1;" : "=r"(u) : "f"(f));
    return __uint_as_float(u);
}
#define SWZ128(o) ((o) ^ (((o) >> 3) & 0x70))
#define CP16(dst, src) asm volatile("cp.async.cg.shared.global [%0], [%1], 16;" :: "r"(dst), "l"(src))

__device__ __forceinline__ void mma_tf32(float* d, const uint32_t* a, const uint32_t* b) {
    asm volatile(
        "mma.sync.aligned.m16n8k8.row.col.f32.tf32.tf32.f32 "
        "{%0,%1,%2,%3}, {%4,%5,%6,%7}, {%8,%9}, {%0,%1,%2,%3};"
        : "+f"(d[0]), "+f"(d[1]), "+f"(d[2]), "+f"(d[3])
        : "r"(a[0]), "r"(a[1]), "r"(a[2]), "r"(a[3]), "r"(b[0]), "r"(b[1]));
}
__device__ __forceinline__ float ldsf(uint32_t a) {
    float v;
    asm volatile("ld.shared.f32 %0, [%1];" : "=f"(v) : "r"(a));
    return v;
}

// ================= FLASH ATTENTION =================
// grid (16 qtiles, 32 bh), block 256 (8 warps x 16 q-rows).
// SMEM float layout: Q[128][68] | K[2][128][68] | V[2][128][72] | mask[2048]
#define FAQ_BYTES 34816
#define FAK_BYTES 34816
#define FAV_BYTES 36864
#define OFF_Q 0
#define OFF_K 34816
#define OFF_V 104448
#define OFF_M 178176
#define FA_SMEM 186368

__global__ void __launch_bounds__(256, 1)
flash_attn(const float* __restrict__ QKV, const int* __restrict__ mask,
           float* __restrict__ out) {
    extern __shared__ char smem[];
    const uint32_t sb = smem_u32(smem);
    int tid = threadIdx.x, wid = tid >> 5, lid = tid & 31;
    int g = lid >> 2, tc = lid & 3;
    int qt = blockIdx.x, bh = blockIdx.y;
    int b = bh >> 4, h = bh & 15;
    int q0 = qt * 128;
    int wq0 = wid * 16;
    const float* base = QKV + (size_t)b * SS * 3072 + h * 64;

    // ---- stage Q + K0 + V0 ----
#pragma unroll
    for (int i = 0; i < 8; i++) {
        int idx = tid + i * 256, r = idx >> 4, c = idx & 15;
        CP16(sb + OFF_Q + r * 272 + c * 16, base + (size_t)(q0 + r) * 3072 + c * 4);
    }
#pragma unroll
    for (int i = 0; i < 8; i++) {
        int idx = tid + i * 256, r = idx >> 4, c = idx & 15;
        CP16(sb + OFF_K + r * 272 + c * 16, base + (size_t)r * 3072 + 1024 + c * 4);
    }
#pragma unroll
    for (int i = 0; i < 8; i++) {
        int idx = tid + i * 256, r = idx >> 4, c = idx & 15;
        CP16(sb + OFF_V + r * 288 + c * 16, base + (size_t)r * 3072 + 2048 + c * 4);
    }
    asm volatile("cp.async.commit_group;" ::: "memory");
    // mask to smem
    int* msmem = (int*)(smem + OFF_M);
#pragma unroll
    for (int i = 0; i < 8; i++) {
        int idx = tid + i * 256;
        msmem[idx] = mask[b * SS + idx];
    }
    asm volatile("cp.async.wait_group 0;" ::: "memory");
    __syncthreads();

    // ---- Q fragments (persist in regs) ----
    uint32_t af[8][4];
    {
        int i8 = lid & 7, t4 = lid >> 3;
        int row = wq0 + i8 + (t4 & 1) * 8;
        uint32_t abase = sb + OFF_Q + row * 272 + (t4 >> 1) * 16;
#pragma unroll
        for (int kc = 0; kc < 8; kc++) {
            asm volatile("ldmatrix.sync.aligned.m8n8.x4.shared.b16 {%0,%1,%2,%3}, [%4];"
                         : "=r"(af[kc][0]), "=r"(af[kc][1]), "=r"(af[kc][2]), "=r"(af[kc][3])
                         : "r"(abase + kc * 32));
        }
    }

    float oacc[8][4];
#pragma unroll
    for (int i = 0; i < 8; i++)
#pragma unroll
        for (int j = 0; j < 4; j++) oacc[i][j] = 0.f;
    float l0 = 0.f, l1 = 0.f, m0 = -INFINITY, m1 = -INFINITY;

    for (int it = 0; it < 16; it++) {
        int buf = it & 1;
        // prefetch next K/V
        if (it + 1 < 16) {
            int kv1 = (it + 1) * 128, nb = buf ^ 1;
#pragma unroll
            for (int i = 0; i < 8; i++) {
                int idx = tid + i * 256, r = idx >> 4, c = idx & 15;
                CP16(sb + OFF_K + nb * FAK_BYTES + r * 272 + c * 16,
                     base + (size_t)(kv1 + r) * 3072 + 1024 + c * 4);
            }
#pragma unroll
            for (int i = 0; i < 8; i++) {
                int idx = tid + i * 256, r = idx >> 4, c = idx & 15;
                CP16(sb + OFF_V + nb * FAV_BYTES + r * 288 + c * 16,
                     base + (size_t)(kv1 + r) * 3072 + 2048 + c * 4);
            }
            asm volatile("cp.async.commit_group;" ::: "memory");
        }
        if (it > 0) {
            if (it + 1 < 16) asm volatile("cp.async.wait_group 1;" ::: "memory");
            else             asm volatile("cp.async.wait_group 0;" ::: "memory");
            __syncthreads();
        }

        int kv0 = it * 128;
        // ---- S = Q @ K^T  (16 n-tiles x 8 k-steps) ----
        float sacc[16][4];
#pragma unroll
        for (int i = 0; i < 16; i++)
#pragma unroll
            for (int j = 0; j < 4; j++) sacc[i][j] = 0.f;
        uint32_t kb = sb + OFF_K + buf * FAK_BYTES;
#pragma unroll
        for (int nt = 0; nt < 16; nt++) {
            uint32_t rowb = kb + (8 * nt + g) * 272 + tc * 4;
#pragma unroll
            for (int kc = 0; kc < 8; kc++) {
                uint32_t bf[2];
                bf[0] = __float_as_uint(ldsf(rowb + kc * 32));
                bf[1] = __float_as_uint(ldsf(rowb + kc * 32 + 16));
                mma_tf32(sacc[nt], af[kc], bf);
            }
        }

        // ---- scale + mask + online softmax ----
        float mt0 = -INFINITY, mt1 = -INFINITY;
#pragma unroll
        for (int nt = 0; nt < 16; nt++) {
            int c0 = kv0 + 8 * nt + 2 * tc;
            int mk0 = msmem[c0], mk1 = msmem[c0 + 1];
            float s0 = sacc[nt][0] * 0.125f, s1 = sacc[nt][1] * 0.125f;
            float s2 = sacc[nt][2] * 0.125f, s3 = sacc[nt][3] * 0.125f;
            if (mk0 == 0) { s0 = -INFINITY; s2 = -INFINITY; }
            if (mk1 == 0) { s1 = -INFINITY; s3 = -INFINITY; }
            sacc[nt][0] = s0; sacc[nt][1] = s1; sacc[nt][2] = s2; sacc[nt][3] = s3;
            mt0 = fmaxf(mt0, fmaxf(s0, s1));
            mt1 = fmaxf(mt1, fmaxf(s2, s3));
        }
        mt0 = fmaxf(mt0, __shfl_xor_sync(0xffffffff, mt0, 1));
        mt0 = fmaxf(mt0, __shfl_xor_sync(0xffffffff, mt0, 2));
        mt1 = fmaxf(mt1, __shfl_xor_sync(0xffffffff, mt1, 1));
        mt1 = fmaxf(mt1, __shfl_xor_sync(0xffffffff, mt1, 2));
        float mn0 = fmaxf(m0, mt0), mn1 = fmaxf(m1, mt1);
        float al0 = __expf(m0 - mn0), al1 = __expf(m1 - mn1);
        l0 *= al0; l1 *= al1;
#pragma unroll
        for (int i = 0; i < 8; i++) {
            oacc[i][0] *= al0; oacc[i][1] *= al0;
            oacc[i][2] *= al1; oacc[i][3] *= al1;
        }
#pragma unroll
        for (int nt = 0; nt < 16; nt++) {
            float p0 = __expf(sacc[nt][0] - mn0);
            float p1 = __expf(sacc[nt][1] - mn0);
            float p2 = __expf(sacc[nt][2] - mn1);
            float p3 = __expf(sacc[nt][3] - mn1);
            l0 += p0 + p1; l1 += p2 + p3;
            sacc[nt][0] = rndf(p0); sacc[nt][1] = rndf(p1);
            sacc[nt][2] = rndf(p2); sacc[nt][3] = rndf(p3);
        }
        m0 = mn0; m1 = mn1;

        // ---- O += P @ V ----
        uint32_t vb = sb + OFF_V + buf * FAV_BYTES;
        int srcA = (lid & ~3) | (tc >> 1);
        int odd = tc & 1;
#pragma unroll
        for (int kc = 0; kc < 16; kc++) {
            float p0 = sacc[kc][0], p1 = sacc[kc][1], p2 = sacc[kc][2], p3 = sacc[kc][3];
            float u0 = __shfl_sync(0xffffffff, p0, srcA);
            float u1 = __shfl_sync(0xffffffff, p1, srcA);
            float w0 = __shfl_sync(0xffffffff, p2, srcA);
            float w1 = __shfl_sync(0xffffffff, p3, srcA);
            float v0 = __shfl_sync(0xffffffff, p0, srcA + 2);
            float v1 = __shfl_sync(0xffffffff, p1, srcA + 2);
            float y0 = __shfl_sync(0xffffffff, p2, srcA + 2);
            float y1 = __shfl_sync(0xffffffff, p3, srcA + 2);
            uint32_t afr[4];
            afr[0] = __float_as_uint(odd ? u1 : u0);
            afr[1] = __float_as_uint(odd ? w1 : w0);
            afr[2] = __float_as_uint(odd ? v1 : v0);
            afr[3] = __float_as_uint(odd ? y1 : y0);
            uint32_t r0b = vb + (8 * kc + tc) * 288 + g * 4;
            uint32_t r1b = vb + (8 * kc + tc + 4) * 288 + g * 4;
#pragma unroll
            for (int nt = 0; nt < 8; nt++) {
                uint32_t bf[2];
                bf[0] = __float_as_uint(ldsf(r0b + nt * 32));
                bf[1] = __float_as_uint(ldsf(r1b + nt * 32));
                mma_tf32(oacc[nt], afr, bf);
            }
        }
        __syncthreads();
    }

    // ---- reduce l across quad (each lane held partial sums of its own cols) ----
    l0 += __shfl_xor_sync(0xffffffff, l0, 1);
    l0 += __shfl_xor_sync(0xffffffff, l0, 2);
    l1 += __shfl_xor_sync(0xffffffff, l1, 1);
    l1 += __shfl_xor_sync(0xffffffff, l1, 2);

    // ---- epilogue: O / l -> attn [tok, D] ----
    float il0 = 1.f / l0, il1 = 1.f / l1;
    int r0 = q0 + wq0 + g, r1 = r0 + 8;
    float* o0 = out + (size_t)(b * SS + r0) * DD + h * 64 + 2 * tc;
    float* o1 = out + (size_t)(b * SS + r1) * DD + h * 64 + 2 * tc;
#pragma unroll
    for (int nt = 0; nt < 8; nt++) {
        *(float2*)(o0 + nt * 8) = make_float2(oacc[nt][0] * il0, oacc[nt][1] * il0);
        *(float2*)(o1 + nt * 8) = make_float2(oacc[nt][2] * il1, oacc[nt][3] * il1);
    }
}

// ---------------- tf32 mma.sync GEMM ----------------
// C[M,N] = A[M,K] @ B[N,K]^T + epilogue.  MODE 0: +bias  1: relu(+bias)
template <int BN, int MODE, bool RND>
__global__ void __launch_bounds__(256)
mma_gemm(const float* __restrict__ A, int lda,
         const float* __restrict__ B, int ldb,
         float* __restrict__ C, int ldc,
         const float* __restrict__ bias, int K) {
    extern __shared__ char smem[];
    constexpr int ABYTES = 128 * 32 * 4;
    constexpr int BBYTES = BN * 32 * 4;
    constexpr int MT = 4;

    const uint32_t sb = smem_u32(smem);
    int tid = threadIdx.x, wid = tid >> 5, lid = tid & 31;
    int m0 = blockIdx.y * 128, n0 = blockIdx.x * BN;

    int wm0 = (wid >> 2) * 64, wn0 = (wid & 3) * 32;

    float acc[MT][4][4];
#pragma unroll
    for (int i = 0; i < MT; i++)
#pragma unroll
        for (int j = 0; j < 4; j++)
#pragma unroll
            for (int r = 0; r < 4; r++) acc[i][j][r] = 0.f;

    const int NC = K >> 5;
    {
        uint32_t ab = sb, bb = sb + 2 * ABYTES;
#pragma unroll
        for (int i = 0; i < 4; i++) {
            int q = tid + i * 256, row = q >> 3, cg = q & 7;
            CP16(ab + SWZ128(q * 16), A + (size_t)(m0 + row) * lda + cg * 4);
        }
#pragma unroll
        for (int i = 0; i < (BN * 8) / 256; i++) {
            int q = tid + i * 256, row = q >> 3, cg = q & 7;
            CP16(bb + SWZ128(q * 16), B + (size_t)(n0 + row) * ldb + cg * 4);
        }
        asm volatile("cp.async.commit_group;" ::: "memory");
    }

    for (int c = 0; c < NC; c++) {
        int buf = c & 1;
        if (c + 1 < NC) {
            int k0 = (c + 1) << 5;
            uint32_t ab = sb + (buf ^ 1) * ABYTES;
            uint32_t bb = sb + 2 * ABYTES + (buf ^ 1) * BBYTES;
#pragma unroll
            for (int i = 0; i < 4; i++) {
                int q = tid + i * 256, row = q >> 3, cg = q & 7;
                CP16(ab + SWZ128(q * 16), A + (size_t)(m0 + row) * lda + k0 + cg * 4);
            }
#pragma unroll
            for (int i = 0; i < (BN * 8) / 256; i++) {
                int q = tid + i * 256, row = q >> 3, cg = q & 7;
                CP16(bb + SWZ128(q * 16), B + (size_t)(n0 + row) * ldb + k0 + cg * 4);
            }
            asm volatile("cp.async.commit_group;" ::: "memory");
            asm volatile("cp.async.wait_group 1;" ::: "memory");
        } else {
            asm volatile("cp.async.wait_group 0;" ::: "memory");
        }
        __syncthreads();

        uint32_t ab = sb + buf * ABYTES;
        uint32_t bb = sb + 2 * ABYTES + buf * BBYTES;
        int i8 = lid & 7, t4 = lid >> 3;
        int g = lid >> 2, tc = lid & 3;
#pragma unroll
        for (int s = 0; s < 4; s++) {
            uint32_t af[MT][4];
#pragma unroll
            for (int mt = 0; mt < MT; mt++) {
                int row = wm0 + mt * 16 + i8 + (t4 & 1) * 8;
                uint32_t addr = ab + SWZ128(row * 128 + (2 * s + (t4 >> 1)) * 16);
                asm volatile("ldmatrix.sync.aligned.m8n8.x4.shared.b16 {%0,%1,%2,%3}, [%4];"
                             : "=r"(af[mt][0]), "=r"(af[mt][1]), "=r"(af[mt][2]), "=r"(af[mt][3])
                             : "r"(addr));
            }
            uint32_t bf[4][2];
#pragma unroll
            for (int nt = 0; nt < 4; nt++) {
                int n = wn0 + nt * 8 + g;
                int byte0 = n * 128 + s * 32 + tc * 4;
                bf[nt][0] = __float_as_uint(ldsf(bb + SWZ128(byte0)));
                bf[nt][1] = __float_as_uint(ldsf(bb + SWZ128(byte0 + 16)));
            }
#pragma unroll
            for (int mt = 0; mt < MT; mt++)
#pragma unroll
                for (int nt = 0; nt < 4; nt++)
                    mma_tf32(acc[mt][nt], af[mt], bf[nt]);
        }
        __syncthreads();
    }

    int g = lid >> 2, tc = lid & 3;
#pragma unroll
    for (int mt = 0; mt < MT; mt++) {
        int row = m0 + wm0 + mt * 16 + g;
#pragma unroll
        for (int nt = 0; nt < 4; nt++) {
            int col = n0 + wn0 + nt * 8 + tc * 2;
            float v00 = acc[mt][nt][0], v01 = acc[mt][nt][1];
            float v10 = acc[mt][nt][2], v11 = acc[mt][nt][3];
            float2 bv = *(const float2*)(bias + col);
            v00 += bv.x; v01 += bv.y; v10 += bv.x; v11 += bv.y;
            if (MODE == 1) {
                v00 = fmaxf(v00, 0.f); v01 = fmaxf(v01, 0.f);
                v10 = fmaxf(v10, 0.f); v11 = fmaxf(v11, 0.f);
            }
            if (RND) {
                v00 = rndf(v00); v01 = rndf(v01); v10 = rndf(v10); v11 = rndf(v11);
            }
            *(float2*)(C + (size_t)row * ldc + col) = make_float2(v00, v01);
            *(float2*)(C + (size_t)(row + 8) * ldc + col) = make_float2(v10, v11);
        }
    }
}

// ---------------- prep kernels ----------------
__global__ void round_copy(const float* __restrict__ in, float* __restrict__ out, int n4) {
    int i = blockIdx.x * blockDim.x + threadIdx.x;
    if (i < n4) {
        float4 v = ((const float4*)in)[i];
        v.x = rndf(v.x); v.y = rndf(v.y); v.z = rndf(v.z); v.w = rndf(v.w);
        ((float4*)out)[i] = v;
    }
}

__global__ void pack_wT(const float* __restrict__ Wq, const float* __restrict__ Wk,
                        const float* __restrict__ Wv) {
    __shared__ float t[32][33];
    int zz = blockIdx.z;
    int which = zz / HH, h = zz % HH;
    const float* W = (which == 0) ? Wq : (which == 1) ? Wk : Wv;
    int d0 = blockIdx.x * 32, e0 = blockIdx.y * 32;
#pragma unroll
    for (int i = 0; i < 32; i += 8)
        t[threadIdx.y + i][threadIdx.x] =
            W[(size_t)h * (DD * 64) + (size_t)(d0 + threadIdx.y + i) * 64 + e0 + threadIdx.x];
    __syncthreads();
#pragma unroll
    for (int i = 0; i < 32; i += 8)
        g_WpackT[(size_t)(which * DD + h * 64 + e0 + threadIdx.y + i) * DD + d0 + threadIdx.x] =
            rndf(t[threadIdx.x][threadIdx.y + i]);
}

__global__ void pack_bias(const float* __restrict__ bq, const float* __restrict__ bk,
                          const float* __restrict__ bv) {
    int i = blockIdx.x * blockDim.x + threadIdx.x;
    if (i < 3 * DD) {
        int which = i / DD, c = i % DD;
        const float* b = (which == 0) ? bq : (which == 1) ? bk : bv;
        g_bpack[i] = b[c];
    }
}

__global__ void transpose_k(const float* __restrict__ in, float* __restrict__ out, int R, int C) {
    __shared__ float t[32][33];
    int c0 = blockIdx.x * 32, r0 = blockIdx.y * 32;
#pragma unroll
    for (int i = 0; i < 32; i += 8)
        t[threadIdx.y + i][threadIdx.x] = in[(size_t)(r0 + threadIdx.y + i) * C + c0 + threadIdx.x];
    __syncthreads();
#pragma unroll
    for (int i = 0; i < 32; i += 8)
        out[(size_t)(c0 + threadIdx.y + i) * R + r0 + threadIdx.x] = rndf(t[threadIdx.x][threadIdx.y + i]);
}

// ---------------- out = xres + alpha*(a-mean)/(std_unbiased+eps) + beta ----------------
template <bool DUAL>
__global__ void add_ln(const float* __restrict__ xres, const float* __restrict__ a,
                       const float* __restrict__ alpha, const float* __restrict__ beta,
                       float* __restrict__ out, float* __restrict__ outr) {
    int row = blockIdx.x;
    int tid = threadIdx.x;
    const float* ap = a + (size_t)row * DD;
    float v[4];
    float lsum = 0.f;
#pragma unroll
    for (int i = 0; i < 4; i++) {
        v[i] = ap[tid + i * 256];
        lsum += v[i];
    }
    __shared__ float red[256];
    red[tid] = lsum;
    __syncthreads();
    for (int s = 128; s > 0; s >>= 1) {
        if (tid < s) red[tid] += red[tid + s];
        __syncthreads();
    }
    float mean = red[0] * (1.f / DD);
    __syncthreads();
    float lss = 0.f;
#pragma unroll
    for (int i = 0; i < 4; i++) {
        float d = v[i] - mean;
        lss += d * d;
    }
    red[tid] = lss;
    __syncthreads();
    for (int s = 128; s > 0; s >>= 1) {
        if (tid < s) red[tid] += red[tid + s];
        __syncthreads();
    }
    float var = red[0] * (1.f / (DD - 1));
    float inv = 1.f / (sqrtf(var) + 1e-6f);
#pragma unroll
    for (int i = 0; i < 4; i++) {
        int c = tid + i * 256;
        float o = xres[(size_t)row * DD + c] + alpha[c] * (v[i] - mean) * inv + beta[c];
        out[(size_t)row * DD + c] = o;
        if (DUAL) outr[(size_t)row * DD + c] = rndf(o);
    }
}

// ---------------- launch ----------------
extern "C" void kernel_launch(void* const* d_in, const int* in_sizes, int n_in,
                              void* d_out, int out_size) {
    const float* x      = (const float*)d_in[0];
    const int*   mask   = (const int*)d_in[1];
    const float* Wq     = (const float*)d_in[2];
    const float* bq     = (const float*)d_in[3];
    const float* Wk     = (const float*)d_in[4];
    const float* bk     = (const float*)d_in[5];
    const float* Wv     = (const float*)d_in[6];
    const float* bv     = (const float*)d_in[7];
    const float* W1     = (const float*)d_in[8];
    const float* b1     = (const float*)d_in[9];
    const float* W2     = (const float*)d_in[10];
    const float* b2     = (const float*)d_in[11];
    const float* alpha1 = (const float*)d_in[12];
    const float* beta1  = (const float*)d_in[13];
    const float* alpha2 = (const float*)d_in[14];
    const float* beta2  = (const float*)d_in[15];
    float* out = (float*)d_out;

    float *xr, *WpackT, *bpack, *W1T, *W2T, *QKV, *attn, *x1, *x1r, *h1, *ffn;
    cudaGetSymbolAddress((void**)&xr,     g_xr);
    cudaGetSymbolAddress((void**)&WpackT, g_WpackT);
    cudaGetSymbolAddress((void**)&bpack,  g_bpack);
    cudaGetSymbolAddress((void**)&W1T,    g_W1T);
    cudaGetSymbolAddress((void**)&W2T,    g_W2T);
    cudaGetSymbolAddress((void**)&QKV,    g_QKV);
    cudaGetSymbolAddress((void**)&attn,   g_attn);
    cudaGetSymbolAddress((void**)&x1,     g_x1);
    cudaGetSymbolAddress((void**)&x1r,    g_x1r);
    cudaGetSymbolAddress((void**)&h1,     g_h1);
    cudaGetSymbolAddress((void**)&ffn,    g_ffn);

    const int SM128 = 2 * 16384 + 2 * 128 * 32 * 4;   // 65536
    cudaFuncSetAttribute(mma_gemm<128, 0, true>,  cudaFuncAttributeMaxDynamicSharedMemorySize, SM128);
    cudaFuncSetAttribute(mma_gemm<128, 0, false>, cudaFuncAttributeMaxDynamicSharedMemorySize, SM128);
    cudaFuncSetAttribute(mma_gemm<128, 1, true>,  cudaFuncAttributeMaxDynamicSharedMemorySize, SM128);
    cudaFuncSetAttribute(flash_attn, cudaFuncAttributeMaxDynamicSharedMemorySize, FA_SMEM);

    // prep
    round_copy<<<(MTOK * DD / 4 + 255) / 256, 256>>>(x, xr, MTOK * DD / 4);
    pack_wT<<<dim3(32, 2, 48), dim3(32, 8)>>>(Wq, Wk, Wv);
    pack_bias<<<12, 256>>>(bq, bk, bv);
    transpose_k<<<dim3(DFF / 32, DD / 32), dim3(32, 8)>>>(W1, W1T, DD, DFF);
    transpose_k<<<dim3(DD / 32, DFF / 32), dim3(32, 8)>>>(W2, W2T, DFF, DD);

    // QKV = xr @ WpackT^T + bias  [4096, 3072], rounded
    mma_gemm<128, 0, true><<<dim3(24, 32), 256, SM128>>>(
        xr, DD, WpackT, DD, QKV, 3 * DD, bpack, DD);

    // fused attention: scores + mask + softmax + P@V
    flash_attn<<<dim3(16, 32), 256, FA_SMEM>>>(QKV, mask, attn);

    // x1 = x + LN1(attn)  (exact + rounded copy)
    add_ln<true><<<MTOK, 256>>>(x, attn, alpha1, beta1, x1, x1r);

    // FFN1: relu(x1r @ W1 + b1), rounded
    mma_gemm<128, 1, true><<<dim3(32, 32), 256, SM128>>>(
        x1r, DD, W1T, DD, h1, DFF, b1, DD);

    // FFN2: h1 @ W2 + b2
    mma_gemm<128, 0, false><<<dim3(8, 32), 256, SM128>>>(
        h1, DFF, W2T, DFF, ffn, DD, b2, DFF);

    // out = x1 + LN2(ffn)
    add_ln<false><<<MTOK, 256>>>(x1, ffn, alpha2, beta2, out, nullptr);
}